// round 5
// baseline (speedup 1.0000x reference)
#include <cuda_runtime.h>
#include <cuda_bf16.h>
#include <cuda_fp8.h>
#include <math.h>
#include <stdint.h>

#define N 8192
#define D 128
#define NB 64                 // N / 128
#define NTILES (NB * (NB + 1) / 2)     // 2080
#define ENC_NEGINF 0x007FFFFFu
#define NEGINF __int_as_float(0xff800000)

// ---------------- scratch (static __device__, no allocation) ----------------
__device__ unsigned g_rowmax[N];   // encoded-float max_{j!=i} (2*G_ij - sq_j)
__device__ float    g_sq[N];
__device__ int      g_flaglist[N];
__device__ int      g_ticket;
__device__ __align__(16) unsigned char g_x8[N * D];   // fp8 e4m3 copy of x (1 MB)

// ---------------- helpers ----------------
__device__ __forceinline__ uint32_t smem_u32(const void* p) {
    uint32_t a;
    asm("{ .reg .u64 t; cvta.to.shared.u64 t, %1; cvt.u32.u64 %0, t; }" : "=r"(a) : "l"(p));
    return a;
}
__device__ __forceinline__ float softplus_var(const float* __restrict__ phi) {
    float p = *phi;
    return (p > 20.f) ? p : log1pf(expf(p));
}
// order-preserving float<->uint encoding for atomicMax
__device__ __forceinline__ unsigned fenc(float f) {
    unsigned u = __float_as_uint(f);
    return (u & 0x80000000u) ? ~u : (u | 0x80000000u);
}
__device__ __forceinline__ float fdec(unsigned e) {
    return (e & 0x80000000u) ? __uint_as_float(e & 0x7FFFFFFFu)
                             : __uint_as_float(~e);
}

__device__ __forceinline__ void ldsm_x4(uint32_t& r0, uint32_t& r1, uint32_t& r2, uint32_t& r3,
                                        uint32_t addr) {
    asm volatile("ldmatrix.sync.aligned.m8n8.x4.shared.b16 {%0,%1,%2,%3}, [%4];"
                 : "=r"(r0), "=r"(r1), "=r"(r2), "=r"(r3) : "r"(addr));
}
// fp8 e4m3 mma: D[16x8] += A[16x32] * B[32x8]
__device__ __forceinline__ void mma_fp8(float* d, const uint32_t* a, uint32_t b0, uint32_t b1) {
    asm volatile(
        "mma.sync.aligned.m16n8k32.row.col.f32.e4m3.e4m3.f32 "
        "{%0,%1,%2,%3}, {%4,%5,%6,%7}, {%8,%9}, {%0,%1,%2,%3};"
        : "+f"(d[0]), "+f"(d[1]), "+f"(d[2]), "+f"(d[3])
        : "r"(a[0]), "r"(a[1]), "r"(a[2]), "r"(a[3]), "r"(b0), "r"(b1));
}

// ---------------- K1: out = x + var*noise ; sq ; fp8 copy ; init ----------------
// 4 rows per warp, loads front-batched for MLP=8
__global__ __launch_bounds__(256) void k1_rows(const float* __restrict__ x,
                                               const float* __restrict__ phi,
                                               const float* __restrict__ noise,
                                               float* __restrict__ out) {
    int tid = threadIdx.x;
    int gw = blockIdx.x * 8 + (tid >> 5);     // global warp id, 2048 warps
    int lane = tid & 31;
    int r0 = gw * 4;
    float var = softplus_var(phi);

    float4 xs[4], ns[4];
    #pragma unroll
    for (int rr = 0; rr < 4; rr++) xs[rr] = ((const float4*)x)[(r0 + rr) * 32 + lane];
    #pragma unroll
    for (int rr = 0; rr < 4; rr++) ns[rr] = ((const float4*)noise)[(r0 + rr) * 32 + lane];

    #pragma unroll
    for (int rr = 0; rr < 4; rr++) {
        float4 xv = xs[rr], nv = ns[rr];
        float4 ov;
        ov.x = fmaf(var, nv.x, xv.x); ov.y = fmaf(var, nv.y, xv.y);
        ov.z = fmaf(var, nv.z, xv.z); ov.w = fmaf(var, nv.w, xv.w);
        ((float4*)out)[(r0 + rr) * 32 + lane] = ov;

        uchar4 q;
        q.x = (unsigned char)__nv_cvt_float_to_fp8(xv.x, __NV_SATFINITE, __NV_E4M3);
        q.y = (unsigned char)__nv_cvt_float_to_fp8(xv.y, __NV_SATFINITE, __NV_E4M3);
        q.z = (unsigned char)__nv_cvt_float_to_fp8(xv.z, __NV_SATFINITE, __NV_E4M3);
        q.w = (unsigned char)__nv_cvt_float_to_fp8(xv.w, __NV_SATFINITE, __NV_E4M3);
        ((uchar4*)g_x8)[(r0 + rr) * 32 + lane] = q;

        float s = xv.x * xv.x + xv.y * xv.y + xv.z * xv.z + xv.w * xv.w;
        #pragma unroll
        for (int o = 16; o; o >>= 1) s += __shfl_xor_sync(0xffffffffu, s, o);
        if (lane == 0) g_sq[r0 + rr] = s;
    }
    if (lane < 4) g_rowmax[r0 + lane] = ENC_NEGINF;
    if (gw == 0 && lane == 0) g_ticket = 0;
}

// ---------------- K2: fp8 mma.sync Gram + fused tail ----------------
// tile: 128 rows x 128 fp8 bytes, padded row stride 144 B
#define ROWB 144

__global__ __launch_bounds__(256, 2)
void k2_gram_mma(const float* __restrict__ x, const float* __restrict__ phi,
                 float* __restrict__ out_scalar) {
    __shared__ __align__(16) unsigned char smA[128 * ROWB];
    __shared__ __align__(16) unsigned char smB[128 * ROWB];
    __shared__ float asq[128], bsq[128];
    __shared__ float rred[128 * 4];
    __shared__ float cred[128 * 2];
    __shared__ int   s_last, s_cnt;
    __shared__ float s_lse;

    uint32_t sa = smem_u32(smA);
    uint32_t sbm = smem_u32(smB);
    int tid = threadIdx.x;
    int wid = tid >> 5, lane = tid & 31;
    int warp_m = wid >> 2;          // 0..1  (64-row band)
    int warp_n = wid & 3;           // 0..3  (32-col band)

    // triangular block decode: b -> (bi, bj), bi <= bj
    int b = blockIdx.x;
    int bi = 0, rem = b;
    while (rem >= NB - bi) { rem -= NB - bi; bi++; }
    int bj = bi + rem;
    bool diag = (bi == bj);

    // ---- load tiles (fp8, 128 B per row = 8 uint4) ----
    const uint4* Ag = (const uint4*)(g_x8 + (size_t)bi * 128 * D);
    const uint4* Bg = (const uint4*)(g_x8 + (size_t)bj * 128 * D);
    #pragma unroll
    for (int it = 0; it < 4; it++) {
        int q = it * 256 + tid;             // 0..1023
        int row = q >> 3, seg = q & 7;
        uint32_t off = (uint32_t)row * ROWB + (uint32_t)seg * 16;
        *(uint4*)(smA + off) = Ag[q];
        *(uint4*)(smB + off) = Bg[q];
    }
    if (tid < 128) asq[tid] = g_sq[bi * 128 + tid];
    else           bsq[tid - 128] = g_sq[bj * 128 + tid - 128];
    __syncthreads();

    // ---- mma mainloop: warp tile 64x32, K=128 (4 k-steps of 32) ----
    int R0 = warp_m * 64;
    int C0 = warp_n * 32;
    float acc[4][4][4];
    #pragma unroll
    for (int mt = 0; mt < 4; mt++)
        #pragma unroll
        for (int nt = 0; nt < 4; nt++)
            #pragma unroll
            for (int r = 0; r < 4; r++) acc[mt][nt][r] = 0.f;

    uint32_t a_row = (uint32_t)(R0 + (lane & 15));
    uint32_t a_kb  = (uint32_t)((lane >> 4) * 16);
    uint32_t b_row = (uint32_t)(C0 + (lane & 7));
    uint32_t b_kb  = (uint32_t)(((lane >> 3) & 3) * 16);

    #pragma unroll
    for (int ktp = 0; ktp < 2; ktp++) {
        // B: x4 covers two k-steps (64 bytes) for each 8-col band
        uint32_t bf[4][4];
        #pragma unroll
        for (int nt = 0; nt < 4; nt++) {
            uint32_t addr = sbm + (b_row + nt * 8) * ROWB + (uint32_t)ktp * 64 + b_kb;
            ldsm_x4(bf[nt][0], bf[nt][1], bf[nt][2], bf[nt][3], addr);
        }
        #pragma unroll
        for (int half = 0; half < 2; half++) {
            uint32_t kbase = (uint32_t)ktp * 64 + (uint32_t)half * 32;
            uint32_t af[4][4];
            #pragma unroll
            for (int mt = 0; mt < 4; mt++) {
                uint32_t addr = sa + (a_row + mt * 16) * ROWB + kbase + a_kb;
                ldsm_x4(af[mt][0], af[mt][1], af[mt][2], af[mt][3], addr);
            }
            #pragma unroll
            for (int mt = 0; mt < 4; mt++)
                #pragma unroll
                for (int nt = 0; nt < 4; nt++)
                    mma_fp8(acc[mt][nt], af[mt], bf[nt][half * 2], bf[nt][half * 2 + 1]);
        }
    }

    // ---- epilogue: fragment rows = lane>>2 (+8), cols = 2*(lane&3) (+1) ----
    int lr = lane >> 2;
    int lc = (lane & 3) * 2;

    float aq[4][2], bq[4][2];
    #pragma unroll
    for (int mt = 0; mt < 4; mt++) {
        aq[mt][0] = asq[R0 + mt * 16 + lr];
        aq[mt][1] = asq[R0 + mt * 16 + lr + 8];
    }
    #pragma unroll
    for (int nt = 0; nt < 4; nt++) {
        bq[nt][0] = bsq[C0 + nt * 8 + lc];
        bq[nt][1] = bsq[C0 + nt * 8 + lc + 1];
    }

    float rm[4][2], cm[4][2];
    #pragma unroll
    for (int i = 0; i < 4; i++) { rm[i][0] = rm[i][1] = NEGINF; cm[i][0] = cm[i][1] = NEGINF; }

    #pragma unroll
    for (int mt = 0; mt < 4; mt++) {
        int r0 = R0 + mt * 16 + lr;
        #pragma unroll
        for (int nt = 0; nt < 4; nt++) {
            int c0 = C0 + nt * 8 + lc;
            #pragma unroll
            for (int rg = 0; rg < 4; rg++) {
                int rr = r0 + (rg >> 1) * 8;
                int cc = c0 + (rg & 1);
                float a = acc[mt][nt][rg];
                float vr = fmaf(2.f, a, -bq[nt][rg & 1]);
                float vc = fmaf(2.f, a, -aq[mt][rg >> 1]);
                if (diag && rr == cc) { vr = NEGINF; vc = NEGINF; }
                rm[mt][rg >> 1] = fmaxf(rm[mt][rg >> 1], vr);
                cm[nt][rg & 1]  = fmaxf(cm[nt][rg & 1], vc);
            }
        }
    }

    #pragma unroll
    for (int mt = 0; mt < 4; mt++)
        #pragma unroll
        for (int h = 0; h < 2; h++) {
            float v = rm[mt][h];
            v = fmaxf(v, __shfl_xor_sync(0xffffffffu, v, 1));
            v = fmaxf(v, __shfl_xor_sync(0xffffffffu, v, 2));
            rm[mt][h] = v;
        }
    #pragma unroll
    for (int nt = 0; nt < 4; nt++)
        #pragma unroll
        for (int h = 0; h < 2; h++) {
            float v = cm[nt][h];
            v = fmaxf(v, __shfl_xor_sync(0xffffffffu, v, 4));
            v = fmaxf(v, __shfl_xor_sync(0xffffffffu, v, 8));
            v = fmaxf(v, __shfl_xor_sync(0xffffffffu, v, 16));
            cm[nt][h] = v;
        }

    if ((lane & 3) == 0) {
        #pragma unroll
        for (int mt = 0; mt < 4; mt++) {
            rred[(R0 + mt * 16 + lr) * 4 + warp_n]     = rm[mt][0];
            rred[(R0 + mt * 16 + lr + 8) * 4 + warp_n] = rm[mt][1];
        }
    }
    if (lane < 4) {
        #pragma unroll
        for (int nt = 0; nt < 4; nt++) {
            cred[(C0 + nt * 8 + lc) * 2 + warp_m]     = cm[nt][0];
            cred[(C0 + nt * 8 + lc + 1) * 2 + warp_m] = cm[nt][1];
        }
    }
    __syncthreads();
    if (tid < 128) {
        float m = fmaxf(fmaxf(rred[tid * 4 + 0], rred[tid * 4 + 1]),
                        fmaxf(rred[tid * 4 + 2], rred[tid * 4 + 3]));
        atomicMax(&g_rowmax[bi * 128 + tid], fenc(m));
    } else {
        int t = tid - 128;
        float m = fmaxf(cred[t * 2 + 0], cred[t * 2 + 1]);
        atomicMax(&g_rowmax[bj * 128 + t], fenc(m));
    }

    // ---- fused tail: last CTA to finish does screen + fallback + reduce ----
    __syncthreads();
    if (tid == 0) {
        __threadfence();
        int t = atomicAdd(&g_ticket, 1);
        s_last = (t == NTILES - 1);
        s_cnt = 0;
        s_lse = 0.f;
    }
    __syncthreads();
    if (!s_last) return;
    __threadfence();   // acquire: all other CTAs' rowmax atomics visible

    float var = softplus_var(phi);
    float half_inv = 0.5f / var;

    // screen all rows
    for (int i = tid; i < N; i += 256) {
        float m = fdec(g_rowmax[i]);
        float zmax = fminf((m - g_sq[i]) * half_inv, 0.f);
        if (zmax > -35.f) {
            int k = atomicAdd(&s_cnt, 1);
            g_flaglist[k] = i;
        }
    }
    __syncthreads();
    int nf = s_cnt;

    // exact fp32 fallback for flagged rows (expected: none)
    float* xi = rred;            // reuse smem
    float* part = cred;
    for (int f = 0; f < nf; f++) {
        int i = g_flaglist[f];
        if (tid < D) xi[tid] = x[(size_t)i * D + tid];
        __syncthreads();
        float sqi = g_sq[i];
        float s = 0.f;
        for (int j = tid; j < N; j += 256) {
            const float* xj = x + (size_t)j * D;
            float dot = 0.f;
            #pragma unroll 8
            for (int k = 0; k < D; k++) dot += xi[k] * xj[k];
            float d2 = fmaxf(sqi + g_sq[j] - 2.f * dot, 0.f);
            s += expf(-d2 * half_inv);
        }
        part[tid] = s;
        __syncthreads();
        for (int o = 128; o; o >>= 1) {
            if (tid < o) part[tid] += part[tid + o];
            __syncthreads();
        }
        if (tid == 0) s_lse += logf(part[0]);
        __syncthreads();
    }

    if (tid == 0) {
        float kde = s_lse / (float)N;   // screened rows contribute log(1) = 0
        float ixt = (logf((float)N) - kde) * 1.4426950408889634f;
        *out_scalar = ixt;
    }
}

// ---------------- launch ----------------
extern "C" void kernel_launch(void* const* d_in, const int* in_sizes, int n_in,
                              void* d_out, int out_size) {
    const float* x     = (const float*)d_in[0];
    const float* phi   = (const float*)d_in[1];
    const float* noise = (const float*)d_in[2];
    float* out = (float*)d_out;

    k1_rows<<<N / 32, 256>>>(x, phi, noise, out);
    k2_gram_mma<<<NTILES, 256>>>(x, phi, out + out_size - 1);
}

// round 6
// speedup vs baseline: 1.2395x; 1.2395x over previous
#include <cuda_runtime.h>
#include <cuda_bf16.h>
#include <cuda_fp8.h>
#include <math.h>
#include <stdint.h>

#define N 8192
#define D 128
#define NB 64                 // N / 128
#define NTILES (NB * (NB + 1) / 2)     // 2080
#define ENC_NEGINF 0x007FFFFFu
#define NEGINF __int_as_float(0xff800000)

// ---------------- scratch (static __device__, no allocation) ----------------
__device__ unsigned g_rowmax[N];   // encoded-float max_{j!=i} (2*G_ij - sq_j)
__device__ float    g_sq[N];
__device__ int      g_flaglist[N];
__device__ __align__(16) unsigned char g_x8[N * D];   // fp8 e4m3 copy of x (1 MB)

// ---------------- helpers ----------------
__device__ __forceinline__ uint32_t smem_u32(const void* p) {
    uint32_t a;
    asm("{ .reg .u64 t; cvta.to.shared.u64 t, %1; cvt.u32.u64 %0, t; }" : "=r"(a) : "l"(p));
    return a;
}
__device__ __forceinline__ float softplus_var(const float* __restrict__ phi) {
    float p = *phi;
    return (p > 20.f) ? p : log1pf(expf(p));
}
// order-preserving float<->uint encoding for atomicMax
__device__ __forceinline__ unsigned fenc(float f) {
    unsigned u = __float_as_uint(f);
    return (u & 0x80000000u) ? ~u : (u | 0x80000000u);
}
__device__ __forceinline__ float fdec(unsigned e) {
    return (e & 0x80000000u) ? __uint_as_float(e & 0x7FFFFFFFu)
                             : __uint_as_float(~e);
}

__device__ __forceinline__ void ldsm_x4(uint32_t& r0, uint32_t& r1, uint32_t& r2, uint32_t& r3,
                                        uint32_t addr) {
    asm volatile("ldmatrix.sync.aligned.m8n8.x4.shared.b16 {%0,%1,%2,%3}, [%4];"
                 : "=r"(r0), "=r"(r1), "=r"(r2), "=r"(r3) : "r"(addr));
}
__device__ __forceinline__ void ldsm_x2(uint32_t& r0, uint32_t& r1, uint32_t addr) {
    asm volatile("ldmatrix.sync.aligned.m8n8.x2.shared.b16 {%0,%1}, [%2];"
                 : "=r"(r0), "=r"(r1) : "r"(addr));
}
// fp8 e4m3 mma: D[16x8] += A[16x32] * B[32x8]
__device__ __forceinline__ void mma_fp8(float* d, const uint32_t* a, const uint32_t* b) {
    asm volatile(
        "mma.sync.aligned.m16n8k32.row.col.f32.e4m3.e4m3.f32 "
        "{%0,%1,%2,%3}, {%4,%5,%6,%7}, {%8,%9}, {%0,%1,%2,%3};"
        : "+f"(d[0]), "+f"(d[1]), "+f"(d[2]), "+f"(d[3])
        : "r"(a[0]), "r"(a[1]), "r"(a[2]), "r"(a[3]), "r"(b[0]), "r"(b[1]));
}

// ---------------- K1: out = x + var*noise ; sq ; fp8 copy ; init ----------------
// 4 rows per warp, loads front-batched for MLP=8
__global__ __launch_bounds__(256) void k1_rows(const float* __restrict__ x,
                                               const float* __restrict__ phi,
                                               const float* __restrict__ noise,
                                               float* __restrict__ out) {
    int tid = threadIdx.x;
    int gw = blockIdx.x * 8 + (tid >> 5);     // global warp id, 2048 warps
    int lane = tid & 31;
    int r0 = gw * 4;
    float var = softplus_var(phi);

    float4 xs[4], ns[4];
    #pragma unroll
    for (int rr = 0; rr < 4; rr++) xs[rr] = ((const float4*)x)[(r0 + rr) * 32 + lane];
    #pragma unroll
    for (int rr = 0; rr < 4; rr++) ns[rr] = ((const float4*)noise)[(r0 + rr) * 32 + lane];

    #pragma unroll
    for (int rr = 0; rr < 4; rr++) {
        float4 xv = xs[rr], nv = ns[rr];
        float4 ov;
        ov.x = fmaf(var, nv.x, xv.x); ov.y = fmaf(var, nv.y, xv.y);
        ov.z = fmaf(var, nv.z, xv.z); ov.w = fmaf(var, nv.w, xv.w);
        ((float4*)out)[(r0 + rr) * 32 + lane] = ov;

        uchar4 q;
        q.x = (unsigned char)__nv_cvt_float_to_fp8(xv.x, __NV_SATFINITE, __NV_E4M3);
        q.y = (unsigned char)__nv_cvt_float_to_fp8(xv.y, __NV_SATFINITE, __NV_E4M3);
        q.z = (unsigned char)__nv_cvt_float_to_fp8(xv.z, __NV_SATFINITE, __NV_E4M3);
        q.w = (unsigned char)__nv_cvt_float_to_fp8(xv.w, __NV_SATFINITE, __NV_E4M3);
        ((uchar4*)g_x8)[(r0 + rr) * 32 + lane] = q;

        float s = xv.x * xv.x + xv.y * xv.y + xv.z * xv.z + xv.w * xv.w;
        #pragma unroll
        for (int o = 16; o; o >>= 1) s += __shfl_xor_sync(0xffffffffu, s, o);
        if (lane == 0) g_sq[r0 + rr] = s;
    }
    if (lane < 4) g_rowmax[r0 + lane] = ENC_NEGINF;
}

// ---------------- K2: fp8 mma.sync Gram, upper triangle, row/col maxes ----------------
// tile: 128 rows x 128 fp8 bytes, padded row stride 144 B (conflict-free ldmatrix)
#define ROWB 144

__global__ __launch_bounds__(256, 2)
void k2_gram_mma() {
    __shared__ __align__(16) unsigned char smA[128 * ROWB];
    __shared__ __align__(16) unsigned char smB[128 * ROWB];
    __shared__ float asq[128], bsq[128];
    __shared__ float rred[128 * 4];
    __shared__ float cred[128 * 2];

    uint32_t sa = smem_u32(smA);
    uint32_t sbm = smem_u32(smB);
    int tid = threadIdx.x;
    int wid = tid >> 5, lane = tid & 31;
    int warp_m = wid >> 2;          // 0..1  (64-row band)
    int warp_n = wid & 3;           // 0..3  (32-col band)

    // triangular block decode: b -> (bi, bj), bi <= bj
    int b = blockIdx.x;
    int bi = 0, rem = b;
    while (rem >= NB - bi) { rem -= NB - bi; bi++; }
    int bj = bi + rem;
    bool diag = (bi == bj);

    // ---- load tiles (fp8, 128 B per row = 8 uint4) ----
    const uint4* Ag = (const uint4*)(g_x8 + (size_t)bi * 128 * D);
    const uint4* Bg = (const uint4*)(g_x8 + (size_t)bj * 128 * D);
    #pragma unroll
    for (int it = 0; it < 4; it++) {
        int q = it * 256 + tid;             // 0..1023
        int row = q >> 3, seg = q & 7;
        uint32_t off = (uint32_t)row * ROWB + (uint32_t)seg * 16;
        *(uint4*)(smA + off) = Ag[q];
        *(uint4*)(smB + off) = Bg[q];
    }
    if (tid < 128) asq[tid] = g_sq[bi * 128 + tid];
    else           bsq[tid - 128] = g_sq[bj * 128 + tid - 128];
    __syncthreads();

    // ---- mma mainloop: warp tile 64x32, K=128 (4 k-steps of 32) ----
    int R0 = warp_m * 64;
    int C0 = warp_n * 32;
    float acc[4][4][4];
    #pragma unroll
    for (int mt = 0; mt < 4; mt++)
        #pragma unroll
        for (int nt = 0; nt < 4; nt++)
            #pragma unroll
            for (int r = 0; r < 4; r++) acc[mt][nt][r] = 0.f;

    // ldmatrix lane addressing (16-byte k-slabs)
    uint32_t a_row = (uint32_t)(R0 + (lane & 15));
    uint32_t a_kb  = (uint32_t)((lane >> 4) * 16);
    uint32_t b_row = (uint32_t)(C0 + (lane & 7));
    uint32_t b_kb  = (uint32_t)(((lane >> 3) & 1) * 16);

    #pragma unroll
    for (int kt = 0; kt < 4; kt++) {
        uint32_t kbase = (uint32_t)kt * 32;   // 32 fp8 bytes per k-step
        uint32_t af[4][4];
        #pragma unroll
        for (int mt = 0; mt < 4; mt++) {
            uint32_t addr = sa + (a_row + mt * 16) * ROWB + kbase + a_kb;
            ldsm_x4(af[mt][0], af[mt][1], af[mt][2], af[mt][3], addr);
        }
        uint32_t bf[4][2];
        #pragma unroll
        for (int nt = 0; nt < 4; nt++) {
            uint32_t addr = sbm + (b_row + nt * 8) * ROWB + kbase + b_kb;
            ldsm_x2(bf[nt][0], bf[nt][1], addr);
        }
        #pragma unroll
        for (int mt = 0; mt < 4; mt++)
            #pragma unroll
            for (int nt = 0; nt < 4; nt++)
                mma_fp8(acc[mt][nt], af[mt], bf[nt]);
    }

    // ---- epilogue: fragment rows = lane>>2 (+8), cols = 2*(lane&3) (+1) ----
    int lr = lane >> 2;
    int lc = (lane & 3) * 2;

    float aq[4][2], bq[4][2];
    #pragma unroll
    for (int mt = 0; mt < 4; mt++) {
        aq[mt][0] = asq[R0 + mt * 16 + lr];
        aq[mt][1] = asq[R0 + mt * 16 + lr + 8];
    }
    #pragma unroll
    for (int nt = 0; nt < 4; nt++) {
        bq[nt][0] = bsq[C0 + nt * 8 + lc];
        bq[nt][1] = bsq[C0 + nt * 8 + lc + 1];
    }

    float rm[4][2], cm[4][2];
    #pragma unroll
    for (int i = 0; i < 4; i++) { rm[i][0] = rm[i][1] = NEGINF; cm[i][0] = cm[i][1] = NEGINF; }

    #pragma unroll
    for (int mt = 0; mt < 4; mt++) {
        int r0 = R0 + mt * 16 + lr;
        #pragma unroll
        for (int nt = 0; nt < 4; nt++) {
            int c0 = C0 + nt * 8 + lc;
            #pragma unroll
            for (int rg = 0; rg < 4; rg++) {
                int rr = r0 + (rg >> 1) * 8;
                int cc = c0 + (rg & 1);
                float a = acc[mt][nt][rg];
                float vr = fmaf(2.f, a, -bq[nt][rg & 1]);
                float vc = fmaf(2.f, a, -aq[mt][rg >> 1]);
                if (diag && rr == cc) { vr = NEGINF; vc = NEGINF; }
                rm[mt][rg >> 1] = fmaxf(rm[mt][rg >> 1], vr);
                cm[nt][rg & 1]  = fmaxf(cm[nt][rg & 1], vc);
            }
        }
    }

    #pragma unroll
    for (int mt = 0; mt < 4; mt++)
        #pragma unroll
        for (int h = 0; h < 2; h++) {
            float v = rm[mt][h];
            v = fmaxf(v, __shfl_xor_sync(0xffffffffu, v, 1));
            v = fmaxf(v, __shfl_xor_sync(0xffffffffu, v, 2));
            rm[mt][h] = v;
        }
    #pragma unroll
    for (int nt = 0; nt < 4; nt++)
        #pragma unroll
        for (int h = 0; h < 2; h++) {
            float v = cm[nt][h];
            v = fmaxf(v, __shfl_xor_sync(0xffffffffu, v, 4));
            v = fmaxf(v, __shfl_xor_sync(0xffffffffu, v, 8));
            v = fmaxf(v, __shfl_xor_sync(0xffffffffu, v, 16));
            cm[nt][h] = v;
        }

    if ((lane & 3) == 0) {
        #pragma unroll
        for (int mt = 0; mt < 4; mt++) {
            rred[(R0 + mt * 16 + lr) * 4 + warp_n]     = rm[mt][0];
            rred[(R0 + mt * 16 + lr + 8) * 4 + warp_n] = rm[mt][1];
        }
    }
    if (lane < 4) {
        #pragma unroll
        for (int nt = 0; nt < 4; nt++) {
            cred[(C0 + nt * 8 + lc) * 2 + warp_m]     = cm[nt][0];
            cred[(C0 + nt * 8 + lc + 1) * 2 + warp_m] = cm[nt][1];
        }
    }
    __syncthreads();
    if (tid < 128) {
        float m = fmaxf(fmaxf(rred[tid * 4 + 0], rred[tid * 4 + 1]),
                        fmaxf(rred[tid * 4 + 2], rred[tid * 4 + 3]));
        atomicMax(&g_rowmax[bi * 128 + tid], fenc(m));
    } else {
        int t = tid - 128;
        float m = fmaxf(cred[t * 2 + 0], cred[t * 2 + 1]);
        atomicMax(&g_rowmax[bj * 128 + t], fenc(m));
    }
}

// ---------------- K3: single-CTA tail: screen -> exact fallback -> reduce ----------------
__global__ __launch_bounds__(1024) void k3_tail(const float* __restrict__ x,
                                                const float* __restrict__ phi,
                                                float* __restrict__ out_scalar) {
    __shared__ float xi[D];
    __shared__ float part[1024];
    __shared__ int   s_cnt;
    __shared__ float s_lse;
    int tid = threadIdx.x;
    float var = softplus_var(phi);
    float half_inv = 0.5f / var;

    if (tid == 0) { s_cnt = 0; s_lse = 0.f; }
    __syncthreads();

    // screen all rows (flagged rows expected: none)
    #pragma unroll
    for (int it = 0; it < 8; it++) {
        int i = it * 1024 + tid;
        float m = fdec(g_rowmax[i]);
        float zmax = fminf((m - g_sq[i]) * half_inv, 0.f);
        if (zmax > -35.f) {
            int k = atomicAdd(&s_cnt, 1);
            g_flaglist[k] = i;
        }
    }
    __syncthreads();
    int nf = s_cnt;

    // exact fp32 fallback
    for (int f = 0; f < nf; f++) {
        int i = g_flaglist[f];
        if (tid < D) xi[tid] = x[(size_t)i * D + tid];
        __syncthreads();
        float sqi = g_sq[i];
        float s = 0.f;
        for (int j = tid; j < N; j += 1024) {
            const float* xj = x + (size_t)j * D;
            float dot = 0.f;
            #pragma unroll 8
            for (int k = 0; k < D; k++) dot += xi[k] * xj[k];
            float d2 = fmaxf(sqi + g_sq[j] - 2.f * dot, 0.f);
            s += expf(-d2 * half_inv);
        }
        part[tid] = s;
        __syncthreads();
        for (int o = 512; o; o >>= 1) {
            if (tid < o) part[tid] += part[tid + o];
            __syncthreads();
        }
        if (tid == 0) s_lse += logf(part[0]);
        __syncthreads();
    }

    if (tid == 0) {
        float kde = s_lse / (float)N;   // screened rows contribute log(1) = 0
        float ixt = (logf((float)N) - kde) * 1.4426950408889634f;
        *out_scalar = ixt;
    }
}

// ---------------- launch ----------------
extern "C" void kernel_launch(void* const* d_in, const int* in_sizes, int n_in,
                              void* d_out, int out_size) {
    const float* x     = (const float*)d_in[0];
    const float* phi   = (const float*)d_in[1];
    const float* noise = (const float*)d_in[2];
    float* out = (float*)d_out;

    k1_rows<<<N / 32, 256>>>(x, phi, noise, out);
    k2_gram_mma<<<NTILES, 256>>>();
    k3_tail<<<1, 1024>>>(x, phi, out + out_size - 1);
}